// round 3
// baseline (speedup 1.0000x reference)
#include <cuda_runtime.h>
#include <math.h>

#define B_ 32
#define N_ 512
#define F_ 32
#define T_ 24
#define K_ 3
#define GC_ 64
#define TC_ 64

typedef unsigned long long ull;

// ---- f32x2 helpers (Blackwell packed fp32) ----
__device__ __forceinline__ ull pk2(float v) {
    ull r;
    asm("mov.b64 %0, {%1, %1};" : "=l"(r) : "f"(v));
    return r;
}
__device__ __forceinline__ ull fma2(ull a, ull b, ull c) {
    ull d;
    asm("fma.rn.f32x2 %0, %1, %2, %3;" : "=l"(d) : "l"(a), "l"(b), "l"(c));
    return d;
}
__device__ __forceinline__ void unpk2(ull v, float& lo, float& hi) {
    unsigned int a, b;
    asm("mov.b64 {%0, %1}, %2;" : "=r"(a), "=r"(b) : "l"(v));
    lo = __uint_as_float(a);
    hi = __uint_as_float(b);
}

// ---------------- scratch (device globals; no allocations allowed) ----------------
__device__ float g_rhs_tT[B_ * T_ * N_];
__device__ float g_tmp_part[B_ * 8 * 768];
__device__ float g_tmp_bt[B_ * T_ * F_];
__device__ float g_lhs_t[B_ * T_ * N_];
__device__ float g_temp_w[B_ * T_ * T_];
__device__ float g_xtemp[B_ * N_ * F_ * T_];
__device__ float g_lhs_s[B_ * N_ * T_];
__device__ float g_rhs_s[B_ * N_ * T_];
__device__ float g_attn[B_ * N_ * N_];
__device__ float g_S[B_ * N_ * N_];
__device__ float g_spat[B_ * N_ * N_];
__device__ float g_projT[N_ * N_];
__device__ float g_H[(size_t)B_ * K_ * N_ * F_ * T_];  // [(b*3+k), n, f*24+t]

// ---------------- K1: rhs_tT[b,t,n] = sum_f ta_w3[f] * x[b,n,f,t] ----------------
__global__ void rhs_t_kernel(const float* __restrict__ x, const float* __restrict__ w3) {
    int bn = blockIdx.x;
    int b = bn >> 9, n = bn & 511;
    __shared__ float row[768];
    const float* xr = x + (size_t)bn * 768;
    for (int i = threadIdx.x; i < 768; i += 128) row[i] = xr[i];
    __syncthreads();
    if (threadIdx.x < 24) {
        int t = threadIdx.x;
        float a = 0.f;
#pragma unroll
        for (int f = 0; f < 32; f++) a += w3[f] * row[f * 24 + t];
        g_rhs_tT[(b * 24 + t) * 512 + n] = a;
    }
}

// ---------------- K2a: partial tmp over n-chunks ----------------
__global__ void tmp_bt_part_kernel(const float* __restrict__ x, const float* __restrict__ w1) {
    int chunk = blockIdx.x;
    int b = blockIdx.y;
    int ft = threadIdx.x;
    const float* xb = x + (size_t)b * 512 * 768;
    int n0 = chunk * 64;
    float a = 0.f;
    for (int n = n0; n < n0 + 64; n++) a += w1[n] * xb[n * 768 + ft];
    g_tmp_part[(b * 8 + chunk) * 768 + ft] = a;
}

// ---------------- K2b: reduce partials ----------------
__global__ void tmp_bt_reduce_kernel() {
    int idx = blockIdx.x * blockDim.x + threadIdx.x;
    if (idx >= B_ * 768) return;
    int b = idx / 768, ft = idx % 768;
    float a = 0.f;
#pragma unroll
    for (int c = 0; c < 8; c++) a += g_tmp_part[(b * 8 + c) * 768 + ft];
    int f = ft / 24, t = ft - f * 24;
    g_tmp_bt[(b * 24 + t) * 32 + f] = a;
}

// ---------------- K3: lhs_t ----------------
__global__ void lhs_t_kernel(const float* __restrict__ w2) {
    int idx = blockIdx.x * blockDim.x + threadIdx.x;
    if (idx >= B_ * T_ * N_) return;
    int n = idx & 511;
    int bt = idx >> 9;
    float a = 0.f;
#pragma unroll
    for (int f = 0; f < 32; f++) a += g_tmp_bt[bt * 32 + f] * w2[f * 512 + n];
    g_lhs_t[idx] = a;
}

// ---------------- K4: temporal attention core ----------------
__global__ void temporal_attn_kernel(const float* __restrict__ ta_bias,
                                     const float* __restrict__ ta_proj) {
    int b = blockIdx.x;
    int tid = threadIdx.x;
    int t = tid / 24, u = tid - (tid / 24) * 24;
    __shared__ float sL[24][129];
    __shared__ float sR[24][129];
    __shared__ float ssig[576];
    __shared__ float sE[576];

    float p = 0.f;
    for (int n0 = 0; n0 < 512; n0 += 128) {
        __syncthreads();
        for (int i = tid; i < 24 * 128; i += 576) {
            int tt = i >> 7, nn = i & 127;
            sL[tt][nn] = g_lhs_t[(b * 24 + tt) * 512 + n0 + nn];
            sR[tt][nn] = g_rhs_tT[(b * 24 + tt) * 512 + n0 + nn];
        }
        __syncthreads();
#pragma unroll 8
        for (int nn = 0; nn < 128; nn++) p += sL[t][nn] * sR[u][nn];
    }
    ssig[t * 24 + u] = 1.f / (1.f + expf(-(p + ta_bias[t * 24 + u])));
    __syncthreads();

    int s = t;
    float e = 0.f;
#pragma unroll
    for (int tt = 0; tt < 24; tt++) e += ta_proj[s * 24 + tt] * ssig[tt * 24 + u];
    sE[s * 24 + u] = e;
    __syncthreads();

    float mx = -1e30f;
#pragma unroll
    for (int ss = 0; ss < 24; ss++) mx = fmaxf(mx, sE[ss * 24 + u]);
    float sum = 0.f;
#pragma unroll
    for (int ss = 0; ss < 24; ss++) sum += expf(sE[ss * 24 + u] - mx);
    g_temp_w[b * 576 + s * 24 + u] = expf(e - mx) / sum;
}

// ---------------- K5: x_temp ----------------
__global__ void xtemp_kernel(const float* __restrict__ x) {
    int idx = blockIdx.x * blockDim.x + threadIdx.x;
    if (idx >= B_ * N_ * F_ * T_) return;
    int u = idx % 24;
    int row = idx / 24;
    int b = row / (512 * 32);
    const float* xr = x + (size_t)row * 24;
    const float* tw = g_temp_w + b * 576;
    float a = 0.f;
#pragma unroll
    for (int t = 0; t < 24; t++) a += xr[t] * tw[t * 24 + u];
    g_xtemp[idx] = a;
}

// ---------------- K6: spatial pre ----------------
__global__ void spre_kernel(const float* __restrict__ wa, const float* __restrict__ wb,
                            const float* __restrict__ wc) {
    int bn = blockIdx.x;
    __shared__ float row[768];
    __shared__ float st2[32];
    const float* xr = g_xtemp + (size_t)bn * 768;
    for (int i = threadIdx.x; i < 768; i += 128) row[i] = xr[i];
    __syncthreads();
    if (threadIdx.x < 32) {
        int f = threadIdx.x;
        float a = 0.f;
#pragma unroll
        for (int t = 0; t < 24; t++) a += row[f * 24 + t] * wa[t];
        st2[f] = a;
    }
    __syncthreads();
    if (threadIdx.x < 24) {
        int t = threadIdx.x;
        float l = 0.f, r = 0.f;
#pragma unroll
        for (int f = 0; f < 32; f++) {
            l += st2[f] * wb[f * 24 + t];
            r += wc[f] * row[f * 24 + t];
        }
        g_lhs_s[bn * 24 + t] = l;
        g_rhs_s[bn * 24 + t] = r;
    }
}

// ---------------- K7: spatial scores + sigmoid ----------------
__global__ void spatial_scores_kernel(const float* __restrict__ sa_bias) {
    int b = blockIdx.z;
    int n0 = blockIdx.y * 16, m0 = blockIdx.x * 16;
    __shared__ float sL[16 * 24], sR[16 * 24];
    int tid = threadIdx.y * 16 + threadIdx.x;
    for (int i = tid; i < 384; i += 256) {
        sL[i] = g_lhs_s[(b * 512 + n0 + i / 24) * 24 + i % 24];
        sR[i] = g_rhs_s[(b * 512 + m0 + i / 24) * 24 + i % 24];
    }
    __syncthreads();
    int n = n0 + threadIdx.y, m = m0 + threadIdx.x;
    float s = 0.f;
#pragma unroll
    for (int t = 0; t < 24; t++) s += sL[threadIdx.y * 24 + t] * sR[threadIdx.x * 24 + t];
    float a = 1.f / (1.f + expf(-(s + sa_bias[n * 512 + m])));
    g_attn[((size_t)b * 512 + n) * 512 + m] = a;
}

// ---------------- transpose sa_proj ----------------
__global__ void transpose512_kernel(const float* __restrict__ in) {
    __shared__ float tile[32][33];
    int x0 = blockIdx.x * 32, y0 = blockIdx.y * 32;
    tile[threadIdx.y][threadIdx.x] = in[(y0 + threadIdx.y) * 512 + x0 + threadIdx.x];
    __syncthreads();
    g_projT[(x0 + threadIdx.y) * 512 + y0 + threadIdx.x] = tile[threadIdx.x][threadIdx.y];
}

// ---------------- K8: S GEMM with f32x2 ----------------
// 64(n) x 128(p) tile, BK=16, 256 threads, 4 x (4 col-pairs) micro in f32x2
__global__ void S_gemm_kernel() {
    int b = blockIdx.z;
    int n0 = blockIdx.y * 64, p0 = blockIdx.x * 128;
    __shared__ __align__(16) float sA[16][64];
    __shared__ __align__(16) float sB[16][128];
    int tid = threadIdx.x;
    int tx = tid & 15, ty = tid >> 4;
    ull acc[4][4] = {};
    const float* attb = g_attn + (size_t)b * 262144;
    int ar = tid >> 4, ac4 = tid & 15;
    int xr = tid >> 5, xc4 = tid & 31;
    for (int m0 = 0; m0 < 512; m0 += 16) {
        {
            float4 v = *(const float4*)(g_projT + (m0 + ar) * 512 + n0 + ac4 * 4);
            *(float4*)&sA[ar][ac4 * 4] = v;
        }
#pragma unroll
        for (int it = 0; it < 2; it++) {
            int r = xr + it * 8;
            float4 v = *(const float4*)(attb + (m0 + r) * 512 + p0 + xc4 * 4);
            *(float4*)&sB[r][xc4 * 4] = v;
        }
        __syncthreads();
#pragma unroll
        for (int mm = 0; mm < 16; mm++) {
            float4 a0 = *(const float4*)&sA[mm][ty * 4];
            ull xv2[4];
#pragma unroll
            for (int i = 0; i < 4; i++) xv2[i] = *(const ull*)&sB[mm][tx * 2 + 32 * i];
            ull pa;
            pa = pk2(a0.x);
#pragma unroll
            for (int i = 0; i < 4; i++) acc[0][i] = fma2(pa, xv2[i], acc[0][i]);
            pa = pk2(a0.y);
#pragma unroll
            for (int i = 0; i < 4; i++) acc[1][i] = fma2(pa, xv2[i], acc[1][i]);
            pa = pk2(a0.z);
#pragma unroll
            for (int i = 0; i < 4; i++) acc[2][i] = fma2(pa, xv2[i], acc[2][i]);
            pa = pk2(a0.w);
#pragma unroll
            for (int i = 0; i < 4; i++) acc[3][i] = fma2(pa, xv2[i], acc[3][i]);
        }
        __syncthreads();
    }
    float* Sb = g_S + (size_t)b * 262144;
#pragma unroll
    for (int a = 0; a < 4; a++) {
        float* p = Sb + (n0 + ty * 4 + a) * 512 + p0 + tx * 2;
#pragma unroll
        for (int i = 0; i < 4; i++) *(ull*)(p + 32 * i) = acc[a][i];
    }
}

// ---------------- K9: column softmax ----------------
__global__ void spat_softmax_kernel() {
    int idx = blockIdx.x * blockDim.x + threadIdx.x;
    if (idx >= B_ * N_) return;
    int b = idx >> 9, p = idx & 511;
    const float* base = g_S + (size_t)b * 262144 + p;
    float* ob = g_spat + (size_t)b * 262144 + p;
    float mx = -1e30f;
    for (int n = 0; n < 512; n++) mx = fmaxf(mx, base[n * 512]);
    float sum = 0.f;
    for (int n = 0; n < 512; n++) {
        float e = expf(base[n * 512] - mx);
        sum += e;
        ob[n * 512] = e;
    }
    float inv = 1.f / sum;
    for (int n = 0; n < 512; n++) ob[n * 512] *= inv;
}

// ---------------- K10: cheb GEMM with f32x2, k-fused ----------------
// 64(n) x 128(j) tile, BK=16, 256 threads, per thread 3k x 4 rows x 4 col-pairs
__global__ void __launch_bounds__(256) cheb_gemm_kernel(const float* __restrict__ cheb,
                                                        const float* __restrict__ x) {
    int b = blockIdx.z;
    int n0 = blockIdx.y * 64, j0 = blockIdx.x * 128;
    __shared__ __align__(16) float sA[3][16][64];
    __shared__ __align__(16) float sX[16][128];
    int tid = threadIdx.x;
    int tx = tid & 15, ty = tid >> 4;
    ull acc[3][4][4] = {};
    const float* spatb = g_spat + (size_t)b * 262144;
    const float* xb = x + (size_t)b * 393216;
    int ar = tid >> 4, ac4 = tid & 15;
    int xr = tid >> 5, xc4 = tid & 31;
    for (int m0 = 0; m0 < 512; m0 += 16) {
        int gi = (m0 + ar) * 512 + n0 + ac4 * 4;
        float4 s4 = *(const float4*)(spatb + gi);
#pragma unroll
        for (int k = 0; k < 3; k++) {
            float4 c4 = *(const float4*)(cheb + k * 262144 + gi);
            float4 r4;
            r4.x = c4.x * s4.x; r4.y = c4.y * s4.y;
            r4.z = c4.z * s4.z; r4.w = c4.w * s4.w;
            *(float4*)&sA[k][ar][ac4 * 4] = r4;
        }
#pragma unroll
        for (int it = 0; it < 2; it++) {
            int r = xr + it * 8;
            float4 v = *(const float4*)(xb + (m0 + r) * 768 + j0 + xc4 * 4);
            *(float4*)&sX[r][xc4 * 4] = v;
        }
        __syncthreads();
#pragma unroll
        for (int mm = 0; mm < 16; mm++) {
            ull xv2[4];
#pragma unroll
            for (int i = 0; i < 4; i++) xv2[i] = *(const ull*)&sX[mm][tx * 2 + 32 * i];
#pragma unroll
            for (int k = 0; k < 3; k++) {
                float4 av = *(const float4*)&sA[k][mm][ty * 4];
                ull pa;
                pa = pk2(av.x);
#pragma unroll
                for (int i = 0; i < 4; i++) acc[k][0][i] = fma2(pa, xv2[i], acc[k][0][i]);
                pa = pk2(av.y);
#pragma unroll
                for (int i = 0; i < 4; i++) acc[k][1][i] = fma2(pa, xv2[i], acc[k][1][i]);
                pa = pk2(av.z);
#pragma unroll
                for (int i = 0; i < 4; i++) acc[k][2][i] = fma2(pa, xv2[i], acc[k][2][i]);
                pa = pk2(av.w);
#pragma unroll
                for (int i = 0; i < 4; i++) acc[k][3][i] = fma2(pa, xv2[i], acc[k][3][i]);
            }
        }
        __syncthreads();
    }
#pragma unroll
    for (int k = 0; k < 3; k++) {
#pragma unroll
        for (int a = 0; a < 4; a++) {
            float* p = g_H + ((size_t)(b * 3 + k) * 512 + n0 + ty * 4 + a) * 768 + j0 + tx * 2;
#pragma unroll
            for (int i = 0; i < 4; i++) *(ull*)(p + 32 * i) = acc[k][a][i];
        }
    }
}

// ---------------- K11: fused epilogue with f32x2 over t-pairs ----------------
// 128 threads: ch = tid>>1 (channel), half = tid&1 (t-halves of 12)
__global__ void final_kernel(const float* __restrict__ x, const float* __restrict__ w_cheb,
                             const float* __restrict__ time_w, const float* __restrict__ time_b,
                             const float* __restrict__ skip_w, const float* __restrict__ skip_b,
                             const float* __restrict__ ln_g, const float* __restrict__ ln_b,
                             float* __restrict__ out) {
    int bn = blockIdx.x;
    int b = bn >> 9, n = bn & 511;
    int tid = threadIdx.x;  // 128
    int ch = tid >> 1, half = tid & 1;
    int tbase = half * 12;
    __shared__ __align__(16) float sH[3 * 32 * 24];
    __shared__ __align__(16) float sx[768];
    __shared__ __align__(16) float sg[64][28];   // padded conv input: idx j holds t=j-1
    __shared__ __align__(16) float sgs[64][28];  // shifted copy: sgs[j] = sg[j+1]
    __shared__ __align__(16) float sv[64 * 24];
    __shared__ float smu[24], srs[24];

    // stage H (3 rows of 768) and x row via float4
    {
        const float4* x4 = (const float4*)(x + (size_t)bn * 768);
        for (int i = tid; i < 192; i += 128) ((float4*)sx)[i] = x4[i];
        for (int i = tid; i < 576; i += 128) {
            int k = i / 192, off = i - k * 192;
            const float4* h4 = (const float4*)(g_H + ((size_t)(b * 3 + k) * 512 + n) * 768);
            ((float4*)sH)[k * 192 + off] = h4[off];
        }
    }
    __syncthreads();

    // ---- phase 1: gcn[ch][t] = relu(sum_kf sH[kf][t] * w_cheb[kf][ch]) ----
    {
        ull acc[6] = {};
        for (int kf = 0; kf < 96; kf++) {
            ull pw = pk2(w_cheb[kf * 64 + ch]);
            const ulonglong2* h2 = (const ulonglong2*)&sH[kf * 24 + tbase];
            ulonglong2 hA = h2[0], hB = h2[1], hC = h2[2];
            acc[0] = fma2(pw, hA.x, acc[0]);
            acc[1] = fma2(pw, hA.y, acc[1]);
            acc[2] = fma2(pw, hB.x, acc[2]);
            acc[3] = fma2(pw, hB.y, acc[3]);
            acc[4] = fma2(pw, hC.x, acc[4]);
            acc[5] = fma2(pw, hC.y, acc[5]);
        }
        if (half == 0) {
            sg[ch][0] = 0.f; sg[ch][25] = 0.f; sg[ch][26] = 0.f; sg[ch][27] = 0.f;
            sgs[ch][24] = 0.f; sgs[ch][25] = 0.f; sgs[ch][26] = 0.f; sgs[ch][27] = 0.f;
        }
#pragma unroll
        for (int i = 0; i < 6; i++) {
            float lo, hi;
            unpk2(acc[i], lo, hi);
            lo = fmaxf(lo, 0.f);
            hi = fmaxf(hi, 0.f);
            int t = 2 * i;
            sg[ch][tbase + t + 1] = lo;
            sg[ch][tbase + t + 2] = hi;
            sgs[ch][tbase + t] = lo;
            sgs[ch][tbase + t + 1] = hi;
        }
    }
    __syncthreads();

    // ---- phase 2: v[ch][t] = relu(timeconv(sg) + skip(sx) + biases) ----
    {
        ull acc[6] = {};
        for (int g = 0; g < 64; g++) {
            // P0..P6: pairs of sg row at even offsets 0..13 (rel tbase)
            const ulonglong2* p2 = (const ulonglong2*)&sg[g][tbase];
            ulonglong2 pA = p2[0], pB = p2[1], pC = p2[2];
            ull P6 = *(const ull*)&sg[g][tbase + 12];
            // Q0..Q5: shifted pairs {g[t+1], g[t+2]}
            const ulonglong2* q2 = (const ulonglong2*)&sgs[g][tbase];
            ulonglong2 qA = q2[0], qB = q2[1], qC = q2[2];
            const float* tw = time_w + (ch * 64 + g) * 3;
            ull w0 = pk2(tw[0]), w1 = pk2(tw[1]), w2 = pk2(tw[2]);
            // tap0
            acc[0] = fma2(w0, pA.x, acc[0]);
            acc[1] = fma2(w0, pA.y, acc[1]);
            acc[2] = fma2(w0, pB.x, acc[2]);
            acc[3] = fma2(w0, pB.y, acc[3]);
            acc[4] = fma2(w0, pC.x, acc[4]);
            acc[5] = fma2(w0, pC.y, acc[5]);
            // tap1 (shifted copy)
            acc[0] = fma2(w1, qA.x, acc[0]);
            acc[1] = fma2(w1, qA.y, acc[1]);
            acc[2] = fma2(w1, qB.x, acc[2]);
            acc[3] = fma2(w1, qB.y, acc[3]);
            acc[4] = fma2(w1, qC.x, acc[4]);
            acc[5] = fma2(w1, qC.y, acc[5]);
            // tap2 (even offsets +2)
            acc[0] = fma2(w2, pA.y, acc[0]);
            acc[1] = fma2(w2, pB.x, acc[1]);
            acc[2] = fma2(w2, pB.y, acc[2]);
            acc[3] = fma2(w2, pC.x, acc[3]);
            acc[4] = fma2(w2, pC.y, acc[4]);
            acc[5] = fma2(w2, P6, acc[5]);
        }
        // skip: pairs of sx row f
        for (int f = 0; f < 32; f++) {
            const ulonglong2* r2 = (const ulonglong2*)&sx[f * 24 + tbase];
            ulonglong2 rA = r2[0], rB = r2[1], rC = r2[2];
            ull pw = pk2(skip_w[ch * 32 + f]);
            acc[0] = fma2(pw, rA.x, acc[0]);
            acc[1] = fma2(pw, rA.y, acc[1]);
            acc[2] = fma2(pw, rB.x, acc[2]);
            acc[3] = fma2(pw, rB.y, acc[3]);
            acc[4] = fma2(pw, rC.x, acc[4]);
            acc[5] = fma2(pw, rC.y, acc[5]);
        }
        float bias = time_b[ch] + skip_b[ch];
#pragma unroll
        for (int i = 0; i < 6; i++) {
            float lo, hi;
            unpk2(acc[i], lo, hi);
            int t = tbase + 2 * i;
            sv[ch * 24 + t] = fmaxf(lo + bias, 0.f);
            sv[ch * 24 + t + 1] = fmaxf(hi + bias, 0.f);
        }
    }
    __syncthreads();

    // ---- layernorm stats over channels per t ----
    if (tid < 24) {
        int t = tid;
        float s = 0.f, s2 = 0.f;
        for (int c = 0; c < 64; c++) {
            float v = sv[c * 24 + t];
            s += v;
            s2 += v * v;
        }
        float mu = s * (1.f / 64.f);
        float var = s2 * (1.f / 64.f) - mu * mu;
        smu[t] = mu;
        srs[t] = rsqrtf(var + 1e-5f);
    }
    __syncthreads();

    float* orow = out + (size_t)bn * 1536;
    for (int i = tid; i < 1536; i += 128) {
        int c = i / 24, t = i - c * 24;
        orow[i] = (sv[i] - smu[t]) * srs[t] * ln_g[c] + ln_b[c];
    }
}

// ---------------- launch ----------------
extern "C" void kernel_launch(void* const* d_in, const int* in_sizes, int n_in,
                              void* d_out, int out_size) {
    const float* x       = (const float*)d_in[0];
    const float* cheb    = (const float*)d_in[1];
    const float* w_cheb  = (const float*)d_in[2];
    const float* sa_wa   = (const float*)d_in[3];
    const float* sa_wb   = (const float*)d_in[4];
    const float* sa_wc   = (const float*)d_in[5];
    const float* sa_bias = (const float*)d_in[6];
    const float* sa_proj = (const float*)d_in[7];
    const float* ta_w1   = (const float*)d_in[8];
    const float* ta_w2   = (const float*)d_in[9];
    const float* ta_w3   = (const float*)d_in[10];
    const float* ta_bias = (const float*)d_in[11];
    const float* ta_proj = (const float*)d_in[12];
    const float* time_w  = (const float*)d_in[13];
    const float* time_b  = (const float*)d_in[14];
    const float* skip_w  = (const float*)d_in[15];
    const float* skip_b  = (const float*)d_in[16];
    const float* ln_g    = (const float*)d_in[17];
    const float* ln_b    = (const float*)d_in[18];
    float* out = (float*)d_out;

    // temporal attention
    rhs_t_kernel<<<B_ * N_, 128>>>(x, ta_w3);
    tmp_bt_part_kernel<<<dim3(8, B_), 768>>>(x, ta_w1);
    tmp_bt_reduce_kernel<<<(B_ * 768 + 255) / 256, 256>>>();
    lhs_t_kernel<<<(B_ * T_ * N_ + 255) / 256, 256>>>(ta_w2);
    temporal_attn_kernel<<<B_, 576>>>(ta_bias, ta_proj);
    xtemp_kernel<<<(B_ * N_ * F_ * T_ + 255) / 256, 256>>>(x);

    // spatial attention
    transpose512_kernel<<<dim3(16, 16), dim3(32, 32)>>>(sa_proj);
    spre_kernel<<<B_ * N_, 128>>>(sa_wa, sa_wb, sa_wc);
    spatial_scores_kernel<<<dim3(32, 32, B_), dim3(16, 16)>>>(sa_bias);
    S_gemm_kernel<<<dim3(4, 8, B_), 256>>>();
    spat_softmax_kernel<<<(B_ * N_ + 255) / 256, 256>>>();

    // chebyshev graph conv (k-fused, f32x2)
    cheb_gemm_kernel<<<dim3(6, 8, B_), 256>>>(cheb, x);

    // fused epilogue
    final_kernel<<<B_ * N_, 128>>>(x, w_cheb, time_w, time_b, skip_w, skip_b, ln_g, ln_b, out);
}

// round 6
// speedup vs baseline: 1.1643x; 1.1643x over previous
#include <cuda_runtime.h>
#include <cuda_bf16.h>
#include <math.h>

#define B_ 32
#define N_ 512
#define F_ 32
#define T_ 24
#define K_ 3
#define GC_ 64
#define TC_ 64

typedef unsigned long long ull;

// ---------------- scratch (device globals; no allocations allowed) ----------------
__device__ float g_rhs_tT[B_ * T_ * N_];
__device__ float g_tmp_part[B_ * 8 * 768];
__device__ float g_tmp_bt[B_ * T_ * F_];
__device__ float g_lhs_t[B_ * T_ * N_];
__device__ float g_temp_w[B_ * T_ * T_];
__device__ float g_xtemp[B_ * N_ * F_ * T_];
__device__ float g_lhs_s[B_ * N_ * T_];
__device__ float g_rhs_s[B_ * N_ * T_];
__device__ float g_attn[B_ * N_ * N_];
__device__ float g_S[B_ * N_ * N_];
__device__ float g_spat[B_ * N_ * N_];
__device__ float g_projT[N_ * N_];
__device__ float g_H[(size_t)B_ * K_ * N_ * F_ * T_];  // [(b*3+k), n, f*24+t]

// bf16 hi/lo operands, row-major [out-dim][m]
__device__ __nv_bfloat16 g_Ah16[(size_t)96 * 512 * 512];  // [(b*3+k)][n][m]
__device__ __nv_bfloat16 g_Al16[(size_t)96 * 512 * 512];
__device__ __nv_bfloat16 g_Xh16[(size_t)32 * 768 * 512];  // [b][j][m]
__device__ __nv_bfloat16 g_Xl16[(size_t)32 * 768 * 512];

// ---- bf16 mma helper ----
#define MMA16816(d, a, b)                                                            \
    asm volatile(                                                                    \
        "mma.sync.aligned.m16n8k16.row.col.f32.bf16.bf16.f32 "                       \
        "{%0,%1,%2,%3}, {%4,%5,%6,%7}, {%8,%9}, {%0,%1,%2,%3};"                      \
        : "+f"((d)[0]), "+f"((d)[1]), "+f"((d)[2]), "+f"((d)[3])                     \
        : "r"((a)[0]), "r"((a)[1]), "r"((a)[2]), "r"((a)[3]), "r"((b)[0]), "r"((b)[1]))

__device__ __forceinline__ unsigned bf16pair(float v0, float v1, float& r0, float& r1) {
    __nv_bfloat16 h0 = __float2bfloat16(v0), h1 = __float2bfloat16(v1);
    r0 = v0 - __bfloat162float(h0);
    r1 = v1 - __bfloat162float(h1);
    return (unsigned)__bfloat16_as_ushort(h0) | ((unsigned)__bfloat16_as_ushort(h1) << 16);
}

// ---------------- K1: rhs_tT ----------------
__global__ void rhs_t_kernel(const float* __restrict__ x, const float* __restrict__ w3) {
    int bn = blockIdx.x;
    int b = bn >> 9, n = bn & 511;
    __shared__ float row[768];
    const float* xr = x + (size_t)bn * 768;
    for (int i = threadIdx.x; i < 768; i += 128) row[i] = xr[i];
    __syncthreads();
    if (threadIdx.x < 24) {
        int t = threadIdx.x;
        float a = 0.f;
#pragma unroll
        for (int f = 0; f < 32; f++) a += w3[f] * row[f * 24 + t];
        g_rhs_tT[(b * 24 + t) * 512 + n] = a;
    }
}

// ---------------- K2a/b ----------------
__global__ void tmp_bt_part_kernel(const float* __restrict__ x, const float* __restrict__ w1) {
    int chunk = blockIdx.x;
    int b = blockIdx.y;
    int ft = threadIdx.x;
    const float* xb = x + (size_t)b * 512 * 768;
    int n0 = chunk * 64;
    float a = 0.f;
    for (int n = n0; n < n0 + 64; n++) a += w1[n] * xb[n * 768 + ft];
    g_tmp_part[(b * 8 + chunk) * 768 + ft] = a;
}
__global__ void tmp_bt_reduce_kernel() {
    int idx = blockIdx.x * blockDim.x + threadIdx.x;
    if (idx >= B_ * 768) return;
    int b = idx / 768, ft = idx % 768;
    float a = 0.f;
#pragma unroll
    for (int c = 0; c < 8; c++) a += g_tmp_part[(b * 8 + c) * 768 + ft];
    int f = ft / 24, t = ft - f * 24;
    g_tmp_bt[(b * 24 + t) * 32 + f] = a;
}

// ---------------- K3 ----------------
__global__ void lhs_t_kernel(const float* __restrict__ w2) {
    int idx = blockIdx.x * blockDim.x + threadIdx.x;
    if (idx >= B_ * T_ * N_) return;
    int n = idx & 511;
    int bt = idx >> 9;
    float a = 0.f;
#pragma unroll
    for (int f = 0; f < 32; f++) a += g_tmp_bt[bt * 32 + f] * w2[f * 512 + n];
    g_lhs_t[idx] = a;
}

// ---------------- K4 ----------------
__global__ void temporal_attn_kernel(const float* __restrict__ ta_bias,
                                     const float* __restrict__ ta_proj) {
    int b = blockIdx.x;
    int tid = threadIdx.x;
    int t = tid / 24, u = tid - (tid / 24) * 24;
    __shared__ float sL[24][129];
    __shared__ float sR[24][129];
    __shared__ float ssig[576];
    __shared__ float sE[576];

    float p = 0.f;
    for (int n0 = 0; n0 < 512; n0 += 128) {
        __syncthreads();
        for (int i = tid; i < 24 * 128; i += 576) {
            int tt = i >> 7, nn = i & 127;
            sL[tt][nn] = g_lhs_t[(b * 24 + tt) * 512 + n0 + nn];
            sR[tt][nn] = g_rhs_tT[(b * 24 + tt) * 512 + n0 + nn];
        }
        __syncthreads();
#pragma unroll 8
        for (int nn = 0; nn < 128; nn++) p += sL[t][nn] * sR[u][nn];
    }
    ssig[t * 24 + u] = 1.f / (1.f + expf(-(p + ta_bias[t * 24 + u])));
    __syncthreads();

    int s = t;
    float e = 0.f;
#pragma unroll
    for (int tt = 0; tt < 24; tt++) e += ta_proj[s * 24 + tt] * ssig[tt * 24 + u];
    sE[s * 24 + u] = e;
    __syncthreads();

    float mx = -1e30f;
#pragma unroll
    for (int ss = 0; ss < 24; ss++) mx = fmaxf(mx, sE[ss * 24 + u]);
    float sum = 0.f;
#pragma unroll
    for (int ss = 0; ss < 24; ss++) sum += expf(sE[ss * 24 + u] - mx);
    g_temp_w[b * 576 + s * 24 + u] = expf(e - mx) / sum;
}

// ---------------- K5 ----------------
__global__ void xtemp_kernel(const float* __restrict__ x) {
    int idx = blockIdx.x * blockDim.x + threadIdx.x;
    if (idx >= B_ * N_ * F_ * T_) return;
    int u = idx % 24;
    int row = idx / 24;
    int b = row / (512 * 32);
    const float* xr = x + (size_t)row * 24;
    const float* tw = g_temp_w + b * 576;
    float a = 0.f;
#pragma unroll
    for (int t = 0; t < 24; t++) a += xr[t] * tw[t * 24 + u];
    g_xtemp[idx] = a;
}

// ---------------- K6 ----------------
__global__ void spre_kernel(const float* __restrict__ wa, const float* __restrict__ wb,
                            const float* __restrict__ wc) {
    int bn = blockIdx.x;
    __shared__ float row[768];
    __shared__ float st2[32];
    const float* xr = g_xtemp + (size_t)bn * 768;
    for (int i = threadIdx.x; i < 768; i += 128) row[i] = xr[i];
    __syncthreads();
    if (threadIdx.x < 32) {
        int f = threadIdx.x;
        float a = 0.f;
#pragma unroll
        for (int t = 0; t < 24; t++) a += row[f * 24 + t] * wa[t];
        st2[f] = a;
    }
    __syncthreads();
    if (threadIdx.x < 24) {
        int t = threadIdx.x;
        float l = 0.f, r = 0.f;
#pragma unroll
        for (int f = 0; f < 32; f++) {
            l += st2[f] * wb[f * 24 + t];
            r += wc[f] * row[f * 24 + t];
        }
        g_lhs_s[bn * 24 + t] = l;
        g_rhs_s[bn * 24 + t] = r;
    }
}

// ---------------- K7 ----------------
__global__ void spatial_scores_kernel(const float* __restrict__ sa_bias) {
    int b = blockIdx.z;
    int n0 = blockIdx.y * 16, m0 = blockIdx.x * 16;
    __shared__ float sL[16 * 24], sR[16 * 24];
    int tid = threadIdx.y * 16 + threadIdx.x;
    for (int i = tid; i < 384; i += 256) {
        sL[i] = g_lhs_s[(b * 512 + n0 + i / 24) * 24 + i % 24];
        sR[i] = g_rhs_s[(b * 512 + m0 + i / 24) * 24 + i % 24];
    }
    __syncthreads();
    int n = n0 + threadIdx.y, m = m0 + threadIdx.x;
    float s = 0.f;
#pragma unroll
    for (int t = 0; t < 24; t++) s += sL[threadIdx.y * 24 + t] * sR[threadIdx.x * 24 + t];
    float a = 1.f / (1.f + expf(-(s + sa_bias[n * 512 + m])));
    g_attn[((size_t)b * 512 + n) * 512 + m] = a;
}

// ---------------- transpose sa_proj ----------------
__global__ void transpose512_kernel(const float* __restrict__ in) {
    __shared__ float tile[32][33];
    int x0 = blockIdx.x * 32, y0 = blockIdx.y * 32;
    tile[threadIdx.y][threadIdx.x] = in[(y0 + threadIdx.y) * 512 + x0 + threadIdx.x];
    __syncthreads();
    g_projT[(x0 + threadIdx.y) * 512 + y0 + threadIdx.x] = tile[threadIdx.x][threadIdx.y];
}

// ---------------- K8: S GEMM (R2 scalar version) ----------------
__global__ void S_gemm_kernel() {
    int b = blockIdx.z;
    int n0 = blockIdx.y * 64, p0 = blockIdx.x * 128;
    __shared__ float sA[16][64];
    __shared__ float sB[16][128];
    int tid = threadIdx.x;
    int tx = tid & 15, ty = tid >> 4;
    float acc[4][8] = {};
    const float* attb = g_attn + (size_t)b * 262144;
    int ar = tid >> 4, ac4 = tid & 15;
    int xr = tid >> 5, xc4 = tid & 31;
    for (int m0 = 0; m0 < 512; m0 += 16) {
        {
            float4 v = *(const float4*)(g_projT + (m0 + ar) * 512 + n0 + ac4 * 4);
            *(float4*)&sA[ar][ac4 * 4] = v;
        }
#pragma unroll
        for (int it = 0; it < 2; it++) {
            int r = xr + it * 8;
            float4 v = *(const float4*)(attb + (m0 + r) * 512 + p0 + xc4 * 4);
            *(float4*)&sB[r][xc4 * 4] = v;
        }
        __syncthreads();
#pragma unroll
        for (int mm = 0; mm < 16; mm++) {
            float4 a0 = *(const float4*)&sA[mm][ty * 4];
            float xv[8];
#pragma unroll
            for (int i = 0; i < 8; i++) xv[i] = sB[mm][tx + 16 * i];
#pragma unroll
            for (int i = 0; i < 8; i++) {
                acc[0][i] += a0.x * xv[i];
                acc[1][i] += a0.y * xv[i];
                acc[2][i] += a0.z * xv[i];
                acc[3][i] += a0.w * xv[i];
            }
        }
        __syncthreads();
    }
    float* Sb = g_S + (size_t)b * 262144;
#pragma unroll
    for (int a = 0; a < 4; a++) {
        float* p = Sb + (n0 + ty * 4 + a) * 512 + p0 + tx;
#pragma unroll
        for (int i = 0; i < 8; i++) p[16 * i] = acc[a][i];
    }
}

// ---------------- K9 ----------------
__global__ void spat_softmax_kernel() {
    int idx = blockIdx.x * blockDim.x + threadIdx.x;
    if (idx >= B_ * N_) return;
    int b = idx >> 9, p = idx & 511;
    const float* base = g_S + (size_t)b * 262144 + p;
    float* ob = g_spat + (size_t)b * 262144 + p;
    float mx = -1e30f;
    for (int n = 0; n < 512; n++) mx = fmaxf(mx, base[n * 512]);
    float sum = 0.f;
    for (int n = 0; n < 512; n++) {
        float e = expf(base[n * 512] - mx);
        sum += e;
        ob[n * 512] = e;
    }
    float inv = 1.f / sum;
    for (int n = 0; n < 512; n++) ob[n * 512] *= inv;
}

// ---------------- convA: A'[n][m] = (cheb[k] * spat[b])^T, bf16 hi/lo ----------------
// grid: (mt 16, nt 16, bk 96), block (32, 8)
__global__ void convA_kernel(const float* __restrict__ cheb) {
    int bk = blockIdx.z;
    int b = bk / 3, k = bk - b * 3;
    int m0 = blockIdx.x * 32, n0 = blockIdx.y * 32;
    __shared__ float tile[32][33];
    const float* ck = cheb + (size_t)k * 262144;
    const float* sp = g_spat + (size_t)b * 262144;
#pragma unroll
    for (int r = 0; r < 4; r++) {
        int m = m0 + threadIdx.y + r * 8;
        int gi = m * 512 + n0 + threadIdx.x;
        tile[threadIdx.y + r * 8][threadIdx.x] = ck[gi] * sp[gi];
    }
    __syncthreads();
    int tid = threadIdx.y * 32 + threadIdx.x;
    unsigned* oh = (unsigned*)g_Ah16;
    unsigned* ol = (unsigned*)g_Al16;
#pragma unroll
    for (int p = 0; p < 2; p++) {
        int pi = tid + p * 256;       // 0..511
        int row = pi >> 4;            // n within tile
        int cp = pi & 15;             // m pair
        float r0, r1;
        unsigned uh = bf16pair(tile[2 * cp][row], tile[2 * cp + 1][row], r0, r1);
        __nv_bfloat16 l0 = __float2bfloat16(r0), l1 = __float2bfloat16(r1);
        unsigned ulv = (unsigned)__bfloat16_as_ushort(l0) |
                       ((unsigned)__bfloat16_as_ushort(l1) << 16);
        size_t base = ((size_t)bk * 512 + n0 + row) * 256 + (m0 >> 1) + cp;
        oh[base] = uh;
        ol[base] = ulv;
    }
}

// ---------------- convX: X^T[j][m] = x[b][m][j], bf16 hi/lo ----------------
// grid: (mt 16, jt 24, b 32), block (32, 8)
__global__ void convX_kernel(const float* __restrict__ x) {
    int b = blockIdx.z;
    int m0 = blockIdx.x * 32, j0 = blockIdx.y * 32;
    __shared__ float tile[32][33];
    const float* xb = x + (size_t)b * 393216;
#pragma unroll
    for (int r = 0; r < 4; r++) {
        int m = m0 + threadIdx.y + r * 8;
        tile[threadIdx.y + r * 8][threadIdx.x] = xb[m * 768 + j0 + threadIdx.x];
    }
    __syncthreads();
    int tid = threadIdx.y * 32 + threadIdx.x;
    unsigned* oh = (unsigned*)g_Xh16;
    unsigned* ol = (unsigned*)g_Xl16;
#pragma unroll
    for (int p = 0; p < 2; p++) {
        int pi = tid + p * 256;
        int row = pi >> 4;  // j within tile
        int cp = pi & 15;   // m pair
        float r0, r1;
        unsigned uh = bf16pair(tile[2 * cp][row], tile[2 * cp + 1][row], r0, r1);
        __nv_bfloat16 l0 = __float2bfloat16(r0), l1 = __float2bfloat16(r1);
        unsigned ulv = (unsigned)__bfloat16_as_ushort(l0) |
                       ((unsigned)__bfloat16_as_ushort(l1) << 16);
        size_t base = ((size_t)b * 768 + j0 + row) * 256 + (m0 >> 1) + cp;
        oh[base] = uh;
        ol[base] = ulv;
    }
}

// ---------------- cheb MMA: H[(b,k),n,j] = sum_m A'[n,m]*X^T[j,m], bf16-split ----------------
// grid (jt 12, nt 8, b 32), 128 threads (4 warps as 2n x 2j), block tile 64n x 64j
__global__ void __launch_bounds__(128) cheb_mma_kernel() {
    __shared__ __align__(16) __nv_bfloat16 sA[3][2][64][40];
    __shared__ __align__(16) __nv_bfloat16 sX[2][64][40];
    int jt = blockIdx.x, nt = blockIdx.y, b = blockIdx.z;
    int n0 = nt * 64, j0 = jt * 64;
    int tid = threadIdx.x;
    int lane = tid & 31, wid = tid >> 5;
    int g = lane >> 2, tg = lane & 3;
    int wn = wid >> 1, wj = wid & 1;

    const __nv_bfloat16* srcA[6];
#pragma unroll
    for (int c = 0; c < 3; c++) {
        size_t base = ((size_t)(b * 3 + c) * 512 + n0) * 512;
        srcA[c * 2] = g_Ah16 + base;
        srcA[c * 2 + 1] = g_Al16 + base;
    }
    const __nv_bfloat16* srcXh = g_Xh16 + ((size_t)b * 768 + j0) * 512;
    const __nv_bfloat16* srcXl = g_Xl16 + ((size_t)b * 768 + j0) * 512;

    float d[3][2][4][4] = {};

    for (int m0 = 0; m0 < 512; m0 += 32) {
        // stage A: 3*2*64 rows x 32 bf16 = 1536 uint4
        for (int i = tid; i < 1536; i += 128) {
            int rowid = i >> 2, quad = i & 3;
            int ch = rowid >> 6;       // 0..5 = (c*2+h)
            int row = rowid & 63;
            uint4 v = *(const uint4*)(srcA[ch] + (size_t)row * 512 + m0 + quad * 8);
            *(uint4*)&sA[ch >> 1][ch & 1][row][quad * 8] = v;
        }
        // stage X: 2*64 rows = 512 uint4
        for (int i = tid; i < 512; i += 128) {
            int rowid = i >> 2, quad = i & 3;
            int h = rowid >> 6, row = rowid & 63;
            const __nv_bfloat16* sp = (h ? srcXl : srcXh) + (size_t)row * 512 + m0 + quad * 8;
            *(uint4*)&sX[h][row][quad * 8] = *(const uint4*)sp;
        }
        __syncthreads();

#pragma unroll
        for (int kk = 0; kk < 32; kk += 16) {
            unsigned xh[4][2], xl[4][2];
#pragma unroll
            for (int ntile = 0; ntile < 4; ntile++) {
                int jr = wj * 32 + ntile * 8 + g;
                xh[ntile][0] = *(const unsigned*)&sX[0][jr][kk + tg * 2];
                xh[ntile][1] = *(const unsigned*)&sX[0][jr][kk + tg * 2 + 8];
                xl[ntile][0] = *(const unsigned*)&sX[1][jr][kk + tg * 2];
                xl[ntile][1] = *(const unsigned*)&sX[1][jr][kk + tg * 2 + 8];
            }
#pragma unroll
            for (int c = 0; c < 3; c++) {
#pragma unroll
                for (int mt = 0; mt < 2; mt++) {
                    int r0 = wn * 32 + mt * 16 + g;
                    unsigned ah[4], al[4];
                    ah[0] = *(const unsigned*)&sA[c][0][r0][kk + tg * 2];
                    ah[1] = *(const unsigned*)&sA[c][0][r0 + 8][kk + tg * 2];
                    ah[2] = *(const unsigned*)&sA[c][0][r0][kk + tg * 2 + 8];
                    ah[3] = *(const unsigned*)&sA[c][0][r0 + 8][kk + tg * 2 + 8];
                    al[0] = *(const unsigned*)&sA[c][1][r0][kk + tg * 2];
                    al[1] = *(const unsigned*)&sA[c][1][r0 + 8][kk + tg * 2];
                    al[2] = *(const unsigned*)&sA[c][1][r0][kk + tg * 2 + 8];
                    al[3] = *(const unsigned*)&sA[c][1][r0 + 8][kk + tg * 2 + 8];
#pragma unroll
                    for (int ntile = 0; ntile < 4; ntile++) {
                        MMA16816(d[c][mt][ntile], ah, xh[ntile]);
                        MMA16816(d[c][mt][ntile], ah, xl[ntile]);
                        MMA16816(d[c][mt][ntile], al, xh[ntile]);
                    }
                }
            }
        }
        __syncthreads();
    }

    // write H
#pragma unroll
    for (int c = 0; c < 3; c++) {
        float* Hb = g_H + (size_t)(b * 3 + c) * 512 * 768;
#pragma unroll
        for (int mt = 0; mt < 2; mt++) {
            int nrow = n0 + wn * 32 + mt * 16 + g;
#pragma unroll
            for (int ntile = 0; ntile < 4; ntile++) {
                int jcol = j0 + wj * 32 + ntile * 8 + tg * 2;
                float2 v0 = make_float2(d[c][mt][ntile][0], d[c][mt][ntile][1]);
                float2 v1 = make_float2(d[c][mt][ntile][2], d[c][mt][ntile][3]);
                *(float2*)&Hb[(size_t)nrow * 768 + jcol] = v0;
                *(float2*)&Hb[(size_t)(nrow + 8) * 768 + jcol] = v1;
            }
        }
    }
}

// ---------------- K11: fused epilogue (R2 scalar version) ----------------
__global__ void final_kernel(const float* __restrict__ x, const float* __restrict__ w_cheb,
                             const float* __restrict__ time_w, const float* __restrict__ time_b,
                             const float* __restrict__ skip_w, const float* __restrict__ skip_b,
                             const float* __restrict__ ln_g, const float* __restrict__ ln_b,
                             float* __restrict__ out) {
    int bn = blockIdx.x;
    int b = bn >> 9, n = bn & 511;
    int tid = threadIdx.x;  // 128
    int ch = tid >> 1, half = tid & 1;
    int tbase = half * 12;
    __shared__ float sH[3 * 32 * 24];
    __shared__ float sx[768];
    __shared__ float sg[64][26];
    __shared__ float sv[64 * 24];
    __shared__ float smu[24], srs[24];

    for (int k = 0; k < 3; k++) {
        const float* src = g_H + ((size_t)(b * 3 + k) * 512 + n) * 768;
        for (int i = tid; i < 768; i += 128) sH[k * 768 + i] = src[i];
    }
    const float* xrow = x + (size_t)bn * 768;
    for (int i = tid; i < 768; i += 128) sx[i] = xrow[i];
    __syncthreads();

    {
        float acc[12];
#pragma unroll
        for (int t = 0; t < 12; t++) acc[t] = 0.f;
        for (int kf = 0; kf < 96; kf++) {
            float w = w_cheb[kf * 64 + ch];
            const float* hr = &sH[kf * 24 + tbase];
#pragma unroll
            for (int t = 0; t < 12; t++) acc[t] += hr[t] * w;
        }
        if (half == 0) { sg[ch][0] = 0.f; sg[ch][25] = 0.f; }
#pragma unroll
        for (int t = 0; t < 12; t++) sg[ch][tbase + t + 1] = fmaxf(acc[t], 0.f);
    }
    __syncthreads();

    {
        float acc[12];
#pragma unroll
        for (int t = 0; t < 12; t++) acc[t] = 0.f;
        for (int g = 0; g < 64; g++) {
            float w0 = time_w[(ch * 64 + g) * 3 + 0];
            float w1 = time_w[(ch * 64 + g) * 3 + 1];
            float w2 = time_w[(ch * 64 + g) * 3 + 2];
            const float* gr = &sg[g][tbase];
#pragma unroll
            for (int t = 0; t < 12; t++) acc[t] += gr[t] * w0 + gr[t + 1] * w1 + gr[t + 2] * w2;
        }
        for (int f = 0; f < 32; f++) {
            float w = skip_w[ch * 32 + f];
            const float* xr = &sx[f * 24 + tbase];
#pragma unroll
            for (int t = 0; t < 12; t++) acc[t] += xr[t] * w;
        }
        float bias = time_b[ch] + skip_b[ch];
#pragma unroll
        for (int t = 0; t < 12; t++) sv[ch * 24 + tbase + t] = fmaxf(acc[t] + bias, 0.f);
    }
    __syncthreads();

    if (tid < 24) {
        int t = tid;
        float s = 0.f, s2 = 0.f;
        for (int c = 0; c < 64; c++) {
            float v = sv[c * 24 + t];
            s += v;
            s2 += v * v;
        }
        float mu = s * (1.f / 64.f);
        float var = s2 * (1.f / 64.f) - mu * mu;
        smu[t] = mu;
        srs[t] = rsqrtf(var + 1e-5f);
    }
    __syncthreads();

    float* orow = out + (size_t)bn * 1536;
    for (int i = tid; i < 1536; i += 128) {
        int c = i / 24, t = i - c * 24;
        orow[i] = (sv[i] - smu[t]) * srs[t] * ln_g[c] + ln_b[c];
    }
}

// ---------------- launch ----------------
extern "C" void kernel_launch(void* const* d_in, const int* in_sizes, int n_in,
                              void* d_out, int out_size) {
    const float* x       = (const float*)d_in[0];
    const float* cheb    = (const float*)d_in[1];
    const float* w_cheb  = (const float*)d_in[2];
    const float* sa_wa   = (const float*)d_in[3];
    const float* sa_wb   = (const float*)d_in[4];
    const float* sa_wc   = (const float*)d_in[5];
    const float* sa_bias = (const float*)d_in[6];
    const float* sa_proj = (const float*)d_in[7];
    const float* ta_w1   = (const float*)d_in[8];
    const float* ta_w2   = (const float*)d_in[9];
    const float* ta_w3   = (const float*)d_in[10];
    const float* ta_bias = (const float*)d_in[11];
    const float* ta_proj = (const float*)d_in[12];
    const float* time_w  = (const float*)d_in[13];
    const float* time_b  = (const float*)d_in[14];
    const float* skip_w  = (const float*)d_in[15];
    const float* skip_b  = (const float*)d_in[16];
    const float* ln_g    = (const float*)d_in[17];
    const float* ln_b    = (const float*)d_in[18];
    float* out = (float*)d_out;

    // temporal attention
    rhs_t_kernel<<<B_ * N_, 128>>>(x, ta_w3);
    tmp_bt_part_kernel<<<dim3(8, B_), 768>>>(x, ta_w1);
    tmp_bt_reduce_kernel<<<(B_ * 768 + 255) / 256, 256>>>();
    lhs_t_kernel<<<(B_ * T_ * N_ + 255) / 256, 256>>>(ta_w2);
    temporal_attn_kernel<<<B_, 576>>>(ta_bias, ta_proj);
    xtemp_kernel<<<(B_ * N_ * F_ * T_ + 255) / 256, 256>>>(x);

    // X operand conversion (independent of attention chain)
    convX_kernel<<<dim3(16, 24, B_), dim3(32, 8)>>>(x);

    // spatial attention
    transpose512_kernel<<<dim3(16, 16), dim3(32, 32)>>>(sa_proj);
    spre_kernel<<<B_ * N_, 128>>>(sa_wa, sa_wb, sa_wc);
    spatial_scores_kernel<<<dim3(32, 32, B_), dim3(16, 16)>>>(sa_bias);
    S_gemm_kernel<<<dim3(4, 8, B_), 256>>>();
    spat_softmax_kernel<<<(B_ * N_ + 255) / 256, 256>>>();

    // chebyshev graph conv via bf16-split mma.sync
    convA_kernel<<<dim3(16, 16, 96), dim3(32, 8)>>>(cheb);
    cheb_mma_kernel<<<dim3(12, 8, B_), 128>>>();

    // fused epilogue
    final_kernel<<<B_ * N_, 128>>>(x, w_cheb, time_w, time_b, skip_w, skip_b, ln_g, ln_b, out);
}

// round 8
// speedup vs baseline: 1.2472x; 1.0712x over previous
#include <cuda_runtime.h>
#include <cuda_bf16.h>
#include <math.h>

#define B_ 32
#define N_ 512
#define F_ 32
#define T_ 24
#define K_ 3
#define GC_ 64
#define TC_ 64

typedef unsigned long long ull;

// ---------------- scratch (device globals; no allocations allowed) ----------------
__device__ float g_rhs_tT[B_ * T_ * N_];
__device__ float g_tmp_part[B_ * 8 * 768];
__device__ float g_tmp_bt[B_ * T_ * F_];
__device__ float g_lhs_t[B_ * T_ * N_];
__device__ float g_temp_w[B_ * T_ * T_];
__device__ float g_xtemp[B_ * N_ * F_ * T_];
__device__ float g_lhs_s[B_ * N_ * T_];
__device__ float g_rhs_s[B_ * N_ * T_];
__device__ float g_S[B_ * N_ * N_];
__device__ float g_spat[B_ * N_ * N_];
__device__ float g_H[(size_t)B_ * K_ * N_ * F_ * T_];  // [(b*3+k), n, f*24+t]

// bf16 hi/lo operands, row-major [out-dim][m]
__device__ __nv_bfloat16 g_Ah16[(size_t)96 * 512 * 512];  // [(b*3+k)][n][m]
__device__ __nv_bfloat16 g_Al16[(size_t)96 * 512 * 512];
__device__ __nv_bfloat16 g_Xh16[(size_t)32 * 768 * 512];  // [b][j][m]
__device__ __nv_bfloat16 g_Xl16[(size_t)32 * 768 * 512];
// S-chain bf16 operands
__device__ __nv_bfloat16 g_projh[N_ * N_];                // [n][m]
__device__ __nv_bfloat16 g_projl[N_ * N_];
__device__ __nv_bfloat16 g_attnTh[(size_t)B_ * N_ * N_];  // [b][p][m] = attn[m][p]
__device__ __nv_bfloat16 g_attnTl[(size_t)B_ * N_ * N_];

// ---- bf16 mma helper ----
#define MMA16816(d, a, b)                                                            \
    asm volatile(                                                                    \
        "mma.sync.aligned.m16n8k16.row.col.f32.bf16.bf16.f32 "                       \
        "{%0,%1,%2,%3}, {%4,%5,%6,%7}, {%8,%9}, {%0,%1,%2,%3};"                      \
        : "+f"((d)[0]), "+f"((d)[1]), "+f"((d)[2]), "+f"((d)[3])                     \
        : "r"((a)[0]), "r"((a)[1]), "r"((a)[2]), "r"((a)[3]), "r"((b)[0]), "r"((b)[1]))

__device__ __forceinline__ unsigned bf16pair(float v0, float v1, float& r0, float& r1) {
    __nv_bfloat16 h0 = __float2bfloat16(v0), h1 = __float2bfloat16(v1);
    r0 = v0 - __bfloat162float(h0);
    r1 = v1 - __bfloat162float(h1);
    return (unsigned)__bfloat16_as_ushort(h0) | ((unsigned)__bfloat16_as_ushort(h1) << 16);
}

// ---------------- K1: rhs_tT ----------------
__global__ void rhs_t_kernel(const float* __restrict__ x, const float* __restrict__ w3) {
    int bn = blockIdx.x;
    int b = bn >> 9, n = bn & 511;
    __shared__ float row[768];
    const float* xr = x + (size_t)bn * 768;
    for (int i = threadIdx.x; i < 768; i += 128) row[i] = xr[i];
    __syncthreads();
    if (threadIdx.x < 24) {
        int t = threadIdx.x;
        float a = 0.f;
#pragma unroll
        for (int f = 0; f < 32; f++) a += w3[f] * row[f * 24 + t];
        g_rhs_tT[(b * 24 + t) * 512 + n] = a;
    }
}

// ---------------- K2a/b ----------------
__global__ void tmp_bt_part_kernel(const float* __restrict__ x, const float* __restrict__ w1) {
    int chunk = blockIdx.x;
    int b = blockIdx.y;
    int ft = threadIdx.x;
    const float* xb = x + (size_t)b * 512 * 768;
    int n0 = chunk * 64;
    float a = 0.f;
    for (int n = n0; n < n0 + 64; n++) a += w1[n] * xb[n * 768 + ft];
    g_tmp_part[(b * 8 + chunk) * 768 + ft] = a;
}
__global__ void tmp_bt_reduce_kernel() {
    int idx = blockIdx.x * blockDim.x + threadIdx.x;
    if (idx >= B_ * 768) return;
    int b = idx / 768, ft = idx % 768;
    float a = 0.f;
#pragma unroll
    for (int c = 0; c < 8; c++) a += g_tmp_part[(b * 8 + c) * 768 + ft];
    int f = ft / 24, t = ft - f * 24;
    g_tmp_bt[(b * 24 + t) * 32 + f] = a;
}

// ---------------- K3 ----------------
__global__ void lhs_t_kernel(const float* __restrict__ w2) {
    int idx = blockIdx.x * blockDim.x + threadIdx.x;
    if (idx >= B_ * T_ * N_) return;
    int n = idx & 511;
    int bt = idx >> 9;
    float a = 0.f;
#pragma unroll
    for (int f = 0; f < 32; f++) a += g_tmp_bt[bt * 32 + f] * w2[f * 512 + n];
    g_lhs_t[idx] = a;
}

// ---------------- K4 ----------------
__global__ void temporal_attn_kernel(const float* __restrict__ ta_bias,
                                     const float* __restrict__ ta_proj) {
    int b = blockIdx.x;
    int tid = threadIdx.x;
    int t = tid / 24, u = tid - (tid / 24) * 24;
    __shared__ float sL[24][129];
    __shared__ float sR[24][129];
    __shared__ float ssig[576];
    __shared__ float sE[576];

    float p = 0.f;
    for (int n0 = 0; n0 < 512; n0 += 128) {
        __syncthreads();
        for (int i = tid; i < 24 * 128; i += 576) {
            int tt = i >> 7, nn = i & 127;
            sL[tt][nn] = g_lhs_t[(b * 24 + tt) * 512 + n0 + nn];
            sR[tt][nn] = g_rhs_tT[(b * 24 + tt) * 512 + n0 + nn];
        }
        __syncthreads();
#pragma unroll 8
        for (int nn = 0; nn < 128; nn++) p += sL[t][nn] * sR[u][nn];
    }
    ssig[t * 24 + u] = 1.f / (1.f + expf(-(p + ta_bias[t * 24 + u])));
    __syncthreads();

    int s = t;
    float e = 0.f;
#pragma unroll
    for (int tt = 0; tt < 24; tt++) e += ta_proj[s * 24 + tt] * ssig[tt * 24 + u];
    sE[s * 24 + u] = e;
    __syncthreads();

    float mx = -1e30f;
#pragma unroll
    for (int ss = 0; ss < 24; ss++) mx = fmaxf(mx, sE[ss * 24 + u]);
    float sum = 0.f;
#pragma unroll
    for (int ss = 0; ss < 24; ss++) sum += expf(sE[ss * 24 + u] - mx);
    g_temp_w[b * 576 + s * 24 + u] = expf(e - mx) / sum;
}

// ---------------- K5 ----------------
__global__ void xtemp_kernel(const float* __restrict__ x) {
    int idx = blockIdx.x * blockDim.x + threadIdx.x;
    if (idx >= B_ * N_ * F_ * T_) return;
    int u = idx % 24;
    int row = idx / 24;
    int b = row / (512 * 32);
    const float* xr = x + (size_t)row * 24;
    const float* tw = g_temp_w + b * 576;
    float a = 0.f;
#pragma unroll
    for (int t = 0; t < 24; t++) a += xr[t] * tw[t * 24 + u];
    g_xtemp[idx] = a;
}

// ---------------- K6 ----------------
__global__ void spre_kernel(const float* __restrict__ wa, const float* __restrict__ wb,
                            const float* __restrict__ wc) {
    int bn = blockIdx.x;
    __shared__ float row[768];
    __shared__ float st2[32];
    const float* xr = g_xtemp + (size_t)bn * 768;
    for (int i = threadIdx.x; i < 768; i += 128) row[i] = xr[i];
    __syncthreads();
    if (threadIdx.x < 32) {
        int f = threadIdx.x;
        float a = 0.f;
#pragma unroll
        for (int t = 0; t < 24; t++) a += row[f * 24 + t] * wa[t];
        st2[f] = a;
    }
    __syncthreads();
    if (threadIdx.x < 24) {
        int t = threadIdx.x;
        float l = 0.f, r = 0.f;
#pragma unroll
        for (int f = 0; f < 32; f++) {
            l += st2[f] * wb[f * 24 + t];
            r += wc[f] * row[f * 24 + t];
        }
        g_lhs_s[bn * 24 + t] = l;
        g_rhs_s[bn * 24 + t] = r;
    }
}

// ---------------- conv_proj: sa_proj -> hi/lo bf16 (row-major [n][m]) ----------------
__global__ void conv_proj_kernel(const float* __restrict__ proj) {
    int i = blockIdx.x * 256 + threadIdx.x;
    float v = proj[i];
    __nv_bfloat16 h = __float2bfloat16(v);
    g_projh[i] = h;
    g_projl[i] = __float2bfloat16(v - __bfloat162float(h));
}

// ---------------- K7: scores + sigmoid -> transposed bf16 hi/lo attnT[p][m] ----------------
__global__ void spatial_scores_kernel(const float* __restrict__ sa_bias) {
    int b = blockIdx.z;
    int n0 = blockIdx.y * 16, m0 = blockIdx.x * 16;
    __shared__ float sL[16 * 24], sR[16 * 24];
    __shared__ float tv[16][17];
    int tid = threadIdx.y * 16 + threadIdx.x;
    for (int i = tid; i < 384; i += 256) {
        sL[i] = g_lhs_s[(b * 512 + n0 + i / 24) * 24 + i % 24];
        sR[i] = g_rhs_s[(b * 512 + m0 + i / 24) * 24 + i % 24];
    }
    __syncthreads();
    int n = n0 + threadIdx.y, m = m0 + threadIdx.x;
    float s = 0.f;
#pragma unroll
    for (int t = 0; t < 24; t++) s += sL[threadIdx.y * 24 + t] * sR[threadIdx.x * 24 + t];
    float a = 1.f / (1.f + expf(-(s + sa_bias[n * 512 + m])));
    // attn[n][m] belongs at attnT[m][n]: stage transpose in smem
    tv[threadIdx.x][threadIdx.y] = a;  // tv[m_local][n_local]
    __syncthreads();
    float v = tv[threadIdx.y][threadIdx.x];  // row = m_local, col = n_local
    __nv_bfloat16 h = __float2bfloat16(v);
    size_t o = ((size_t)b * 512 + m0 + threadIdx.y) * 512 + n0 + threadIdx.x;
    g_attnTh[o] = h;
    g_attnTl[o] = __float2bfloat16(v - __bfloat162float(h));
}

// ---------------- K8: S via bf16-split mma: S[n,p] = sum_m proj[n,m]*attnT[p,m] ----------------
// grid (pt 8, nt 8, b 32), 128 threads (4 warps 2n x 2p), tile 64n x 64p
__global__ void __launch_bounds__(128) S_mma_kernel() {
    __shared__ __align__(16) __nv_bfloat16 sP[2][64][40];
    __shared__ __align__(16) __nv_bfloat16 sB[2][64][40];
    int pt = blockIdx.x, nt = blockIdx.y, b = blockIdx.z;
    int n0 = nt * 64, p0 = pt * 64;
    int tid = threadIdx.x;
    int lane = tid & 31, wid = tid >> 5;
    int g = lane >> 2, tg = lane & 3;
    int wn = wid >> 1, wp = wid & 1;

    const __nv_bfloat16* srcP[2] = {g_projh + (size_t)n0 * 512, g_projl + (size_t)n0 * 512};
    const __nv_bfloat16* srcB[2] = {g_attnTh + ((size_t)b * 512 + p0) * 512,
                                    g_attnTl + ((size_t)b * 512 + p0) * 512};

    float d[2][4][4] = {};

    for (int m0 = 0; m0 < 512; m0 += 32) {
        for (int i = tid; i < 512; i += 128) {
            int rowid = i >> 2, quad = i & 3;
            int h = rowid >> 6, row = rowid & 63;
            *(uint4*)&sP[h][row][quad * 8] =
                *(const uint4*)(srcP[h] + (size_t)row * 512 + m0 + quad * 8);
        }
        for (int i = tid; i < 512; i += 128) {
            int rowid = i >> 2, quad = i & 3;
            int h = rowid >> 6, row = rowid & 63;
            *(uint4*)&sB[h][row][quad * 8] =
                *(const uint4*)(srcB[h] + (size_t)row * 512 + m0 + quad * 8);
        }
        __syncthreads();

#pragma unroll
        for (int kk = 0; kk < 32; kk += 16) {
            unsigned bh[4][2], bl[4][2];
#pragma unroll
            for (int p4 = 0; p4 < 4; p4++) {
                int pr = wp * 32 + p4 * 8 + g;
                bh[p4][0] = *(const unsigned*)&sB[0][pr][kk + tg * 2];
                bh[p4][1] = *(const unsigned*)&sB[0][pr][kk + tg * 2 + 8];
                bl[p4][0] = *(const unsigned*)&sB[1][pr][kk + tg * 2];
                bl[p4][1] = *(const unsigned*)&sB[1][pr][kk + tg * 2 + 8];
            }
#pragma unroll
            for (int mt = 0; mt < 2; mt++) {
                int r0 = wn * 32 + mt * 16 + g;
                unsigned ah[4], al[4];
                ah[0] = *(const unsigned*)&sP[0][r0][kk + tg * 2];
                ah[1] = *(const unsigned*)&sP[0][r0 + 8][kk + tg * 2];
                ah[2] = *(const unsigned*)&sP[0][r0][kk + tg * 2 + 8];
                ah[3] = *(const unsigned*)&sP[0][r0 + 8][kk + tg * 2 + 8];
                al[0] = *(const unsigned*)&sP[1][r0][kk + tg * 2];
                al[1] = *(const unsigned*)&sP[1][r0 + 8][kk + tg * 2];
                al[2] = *(const unsigned*)&sP[1][r0][kk + tg * 2 + 8];
                al[3] = *(const unsigned*)&sP[1][r0 + 8][kk + tg * 2 + 8];
#pragma unroll
                for (int p4 = 0; p4 < 4; p4++) {
                    MMA16816(d[mt][p4], ah, bh[p4]);
                    MMA16816(d[mt][p4], ah, bl[p4]);
                    MMA16816(d[mt][p4], al, bh[p4]);
                }
            }
        }
        __syncthreads();
    }

    float* Sb = g_S + (size_t)b * 262144;
#pragma unroll
    for (int mt = 0; mt < 2; mt++) {
        int nrow = n0 + wn * 32 + mt * 16 + g;
#pragma unroll
        for (int p4 = 0; p4 < 4; p4++) {
            int pcol = p0 + wp * 32 + p4 * 8 + tg * 2;
            *(float2*)&Sb[(size_t)nrow * 512 + pcol] = make_float2(d[mt][p4][0], d[mt][p4][1]);
            *(float2*)&Sb[(size_t)(nrow + 8) * 512 + pcol] = make_float2(d[mt][p4][2], d[mt][p4][3]);
        }
    }
}

// ---------------- K9: column softmax ----------------
__global__ void spat_softmax_kernel() {
    int idx = blockIdx.x * blockDim.x + threadIdx.x;
    if (idx >= B_ * N_) return;
    int b = idx >> 9, p = idx & 511;
    const float* base = g_S + (size_t)b * 262144 + p;
    float* ob = g_spat + (size_t)b * 262144 + p;
    float mx = -1e30f;
    for (int n = 0; n < 512; n++) mx = fmaxf(mx, base[n * 512]);
    float sum = 0.f;
    for (int n = 0; n < 512; n++) {
        float e = expf(base[n * 512] - mx);
        sum += e;
        ob[n * 512] = e;
    }
    float inv = 1.f / sum;
    for (int n = 0; n < 512; n++) ob[n * 512] *= inv;
}

// ---------------- convA: A'[n][m] = (cheb[k] * spat[b])^T, bf16 hi/lo ----------------
// grid: (mt 16, nt 16, bk 96), block (32, 8)
__global__ void convA_kernel(const float* __restrict__ cheb) {
    int bk = blockIdx.z;
    int b = bk / 3, k = bk - b * 3;
    int m0 = blockIdx.x * 32, n0 = blockIdx.y * 32;
    __shared__ float tile[32][33];
    const float* ck = cheb + (size_t)k * 262144;
    const float* sp = g_spat + (size_t)b * 262144;
#pragma unroll
    for (int r = 0; r < 4; r++) {
        int m = m0 + threadIdx.y + r * 8;
        int gi = m * 512 + n0 + threadIdx.x;
        tile[threadIdx.y + r * 8][threadIdx.x] = ck[gi] * sp[gi];
    }
    __syncthreads();
    int tid = threadIdx.y * 32 + threadIdx.x;
    unsigned* oh = (unsigned*)g_Ah16;
    unsigned* ol = (unsigned*)g_Al16;
#pragma unroll
    for (int p = 0; p < 2; p++) {
        int pi = tid + p * 256;       // 0..511
        int row = pi >> 4;            // n within tile
        int cp = pi & 15;             // m pair
        float r0, r1;
        unsigned uh = bf16pair(tile[2 * cp][row], tile[2 * cp + 1][row], r0, r1);
        __nv_bfloat16 l0 = __float2bfloat16(r0), l1 = __float2bfloat16(r1);
        unsigned ulv = (unsigned)__bfloat16_as_ushort(l0) |
                       ((unsigned)__bfloat16_as_ushort(l1) << 16);
        size_t base = ((size_t)bk * 512 + n0 + row) * 256 + (m0 >> 1) + cp;
        oh[base] = uh;
        ol[base] = ulv;
    }
}

// ---------------- convX: X^T[j][m] = x[b][m][j], bf16 hi/lo ----------------
// grid: (mt 16, jt 24, b 32), block (32, 8)
__global__ void convX_kernel(const float* __restrict__ x) {
    int b = blockIdx.z;
    int m0 = blockIdx.x * 32, j0 = blockIdx.y * 32;
    __shared__ float tile[32][33];
    const float* xb = x + (size_t)b * 393216;
#pragma unroll
    for (int r = 0; r < 4; r++) {
        int m = m0 + threadIdx.y + r * 8;
        tile[threadIdx.y + r * 8][threadIdx.x] = xb[m * 768 + j0 + threadIdx.x];
    }
    __syncthreads();
    int tid = threadIdx.y * 32 + threadIdx.x;
    unsigned* oh = (unsigned*)g_Xh16;
    unsigned* ol = (unsigned*)g_Xl16;
#pragma unroll
    for (int p = 0; p < 2; p++) {
        int pi = tid + p * 256;
        int row = pi >> 4;  // j within tile
        int cp = pi & 15;   // m pair
        float r0, r1;
        unsigned uh = bf16pair(tile[2 * cp][row], tile[2 * cp + 1][row], r0, r1);
        __nv_bfloat16 l0 = __float2bfloat16(r0), l1 = __float2bfloat16(r1);
        unsigned ulv = (unsigned)__bfloat16_as_ushort(l0) |
                       ((unsigned)__bfloat16_as_ushort(l1) << 16);
        size_t base = ((size_t)b * 768 + j0 + row) * 256 + (m0 >> 1) + cp;
        oh[base] = uh;
        ol[base] = ulv;
    }
}

// ---------------- cheb MMA: H[(b,k),n,j] = sum_m A'[n,m]*X^T[j,m], bf16-split ----------------
// grid (jt 12, nt 8, b 32), 128 threads (4 warps as 2n x 2j), block tile 64n x 64j
__global__ void __launch_bounds__(128) cheb_mma_kernel() {
    __shared__ __align__(16) __nv_bfloat16 sA[3][2][64][40];
    __shared__ __align__(16) __nv_bfloat16 sX[2][64][40];
    int jt = blockIdx.x, nt = blockIdx.y, b = blockIdx.z;
    int n0 = nt * 64, j0 = jt * 64;
    int tid = threadIdx.x;
    int lane = tid & 31, wid = tid >> 5;
    int g = lane >> 2, tg = lane & 3;
    int wn = wid >> 1, wj = wid & 1;

    const __nv_bfloat16* srcA[6];
#pragma unroll
    for (int c = 0; c < 3; c++) {
        size_t base = ((size_t)(b * 3 + c) * 512 + n0) * 512;
        srcA[c * 2] = g_Ah16 + base;
        srcA[c * 2 + 1] = g_Al16 + base;
    }
    const __nv_bfloat16* srcXh = g_Xh16 + ((size_t)b * 768 + j0) * 512;
    const __nv_bfloat16* srcXl = g_Xl16 + ((size_t)b * 768 + j0) * 512;

    float d[3][2][4][4] = {};

    for (int m0 = 0; m0 < 512; m0 += 32) {
        for (int i = tid; i < 1536; i += 128) {
            int rowid = i >> 2, quad = i & 3;
            int ch = rowid >> 6;
            int row = rowid & 63;
            uint4 v = *(const uint4*)(srcA[ch] + (size_t)row * 512 + m0 + quad * 8);
            *(uint4*)&sA[ch >> 1][ch & 1][row][quad * 8] = v;
        }
        for (int i = tid; i < 512; i += 128) {
            int rowid = i >> 2, quad = i & 3;
            int h = rowid >> 6, row = rowid & 63;
            const __nv_bfloat16* sp = (h ? srcXl : srcXh) + (size_t)row * 512 + m0 + quad * 8;
            *(uint4*)&sX[h][row][quad * 8] = *(const uint4*)sp;
        }
        __syncthreads();

#pragma unroll
        for (int kk = 0; kk < 32; kk += 16) {
            unsigned xh[4][2], xl[4][2];
#pragma unroll
            for (int ntile = 0; ntile < 4; ntile++) {
                int jr = wj * 32 + ntile * 8 + g;
                xh[ntile][0] = *(const unsigned*)&sX[0][jr][kk + tg * 2];
                xh[ntile][1] = *(const unsigned*)&sX[0][jr][kk + tg * 2 + 8];
                xl[ntile][0] = *(const unsigned*)&sX[1][jr][kk + tg * 2];
                xl[ntile][1] = *(const unsigned*)&sX[1][jr][kk + tg * 2 + 8];
            }
#pragma unroll
            for (int c = 0; c < 3; c++) {
#pragma unroll
                for (int mt = 0; mt < 2; mt++) {
                    int r0 = wn * 32 + mt * 16 + g;
                    unsigned ah[4], al[4];
                    ah[0] = *(const unsigned*)&sA[c][0][r0][kk + tg * 2];
                    ah[1] = *(const unsigned*)&sA[c][0][r0 + 8][kk + tg * 2];
                    ah[2] = *(const unsigned*)&sA[c][0][r0][kk + tg * 2 + 8];
                    ah[3] = *(const unsigned*)&sA[c][0][r0 + 8][kk + tg * 2 + 8];
                    al[0] = *(const unsigned*)&sA[c][1][r0][kk + tg * 2];
                    al[1] = *(const unsigned*)&sA[c][1][r0 + 8][kk + tg * 2];
                    al[2] = *(const unsigned*)&sA[c][1][r0][kk + tg * 2 + 8];
                    al[3] = *(const unsigned*)&sA[c][1][r0 + 8][kk + tg * 2 + 8];
#pragma unroll
                    for (int ntile = 0; ntile < 4; ntile++) {
                        MMA16816(d[c][mt][ntile], ah, xh[ntile]);
                        MMA16816(d[c][mt][ntile], ah, xl[ntile]);
                        MMA16816(d[c][mt][ntile], al, xh[ntile]);
                    }
                }
            }
        }
        __syncthreads();
    }

#pragma unroll
    for (int c = 0; c < 3; c++) {
        float* Hb = g_H + (size_t)(b * 3 + c) * 512 * 768;
#pragma unroll
        for (int mt = 0; mt < 2; mt++) {
            int nrow = n0 + wn * 32 + mt * 16 + g;
#pragma unroll
            for (int ntile = 0; ntile < 4; ntile++) {
                int jcol = j0 + wj * 32 + ntile * 8 + tg * 2;
                float2 v0 = make_float2(d[c][mt][ntile][0], d[c][mt][ntile][1]);
                float2 v1 = make_float2(d[c][mt][ntile][2], d[c][mt][ntile][3]);
                *(float2*)&Hb[(size_t)nrow * 768 + jcol] = v0;
                *(float2*)&Hb[(size_t)(nrow + 8) * 768 + jcol] = v1;
            }
        }
    }
}

// ---------------- K11: fused epilogue ----------------
__global__ void final_kernel(const float* __restrict__ x, const float* __restrict__ w_cheb,
                             const float* __restrict__ time_w, const float* __restrict__ time_b,
                             const float* __restrict__ skip_w, const float* __restrict__ skip_b,
                             const float* __restrict__ ln_g, const float* __restrict__ ln_b,
                             float* __restrict__ out) {
    int bn = blockIdx.x;
    int b = bn >> 9, n = bn & 511;
    int tid = threadIdx.x;  // 128
    int ch = tid >> 1, half = tid & 1;
    int tbase = half * 12;
    __shared__ float sH[3 * 32 * 24];
    __shared__ float sx[768];
    __shared__ float sg[64][26];
    __shared__ float sv[64 * 24];
    __shared__ float smu[24], srs[24];

    for (int k = 0; k < 3; k++) {
        const float* src = g_H + ((size_t)(b * 3 + k) * 512 + n) * 768;
        for (int i = tid; i < 768; i += 128) sH[k * 768 + i] = src[i];
    }
    const float* xrow = x + (size_t)bn * 768;
    for (int i = tid; i < 768; i += 128) sx[i] = xrow[i];
    __syncthreads();

    {
        float acc[12];
#pragma unroll
        for (int t = 0; t < 12; t++) acc[t] = 0.f;
        for (int kf = 0; kf < 96; kf++) {
            float w = w_cheb[kf * 64 + ch];
            const float* hr = &sH[kf * 24 + tbase];
#pragma unroll
            for (int t = 0; t < 12; t++) acc[t] += hr[t] * w;
        }
        if (half == 0) { sg[ch][0] = 0.f; sg[ch][25] = 0.f; }
#pragma unroll
        for (int t = 0; t < 12; t++) sg[ch][tbase + t + 1] = fmaxf(acc[t], 0.f);
    }
    __syncthreads();

    {
        float acc[12];
#pragma unroll
        for (int t = 0; t < 12; t++) acc[t] = 0.f;
        for (int g = 0; g < 64; g++) {
            float w0 = time_w[(ch * 64 + g) * 3 + 0];
            float w1 = time_w[(ch * 64 + g) * 3 + 1];
            float w2 = time_w[(ch * 64 + g) * 3 + 2];
            const float* gr = &sg[g][tbase];
#pragma unroll
            for (int t = 0; t < 12; t++) acc[t] += gr[t] * w0 + gr[t + 1] * w1 + gr[t + 2] * w2;
        }
        for (int f = 0; f < 32; f++) {
            float w = skip_w[ch * 32 + f];
            const float* xr = &sx[f * 24 + tbase];
#pragma unroll
            for (int t = 0; t < 12; t++) acc[t] += xr[t] * w;
        }
        float bias = time_b[ch] + skip_b[ch];
#pragma unroll
        for (int t = 0; t < 12; t++) sv[ch * 24 + tbase + t] = fmaxf(acc[t] + bias, 0.f);
    }
    __syncthreads();

    if (tid < 24) {
        int t = tid;
        float s = 0.f, s2 = 0.f;
        for (int c = 0; c < 64; c++) {
            float v = sv[c * 24 + t];
            s += v;
            s2 += v * v;
        }
        float mu = s * (1.f / 64.f);
        float var = s2 * (1.f / 64.f) - mu * mu;
        smu[t] = mu;
        srs[t] = rsqrtf(var + 1e-5f);
    }
    __syncthreads();

    float* orow = out + (size_t)bn * 1536;
    for (int i = tid; i < 1536; i += 128) {
        int c = i / 24, t = i - c * 24;
        orow[i] = (sv[i] - smu[t]) * srs[t] * ln_g[c] + ln_b[c];
    }
}

// ---------------- launch ----------------
extern "C" void kernel_launch(void* const* d_in, const int* in_sizes, int n_in,
                              void* d_out, int out_size) {
    const float* x       = (const float*)d_in[0];
    const float* cheb    = (const float*)d_in[1];
    const float* w_cheb  = (const float*)d_in[2];
    const float* sa_wa   = (const float*)d_in[3];
    const float* sa_wb   = (const float*)d_in[4];
    const float* sa_wc   = (const float*)d_in[5];
    const float* sa_bias = (const float*)d_in[6];
    const float* sa_proj = (const float*)d_in[7];
    const float* ta_w1   = (const float*)d_in[8];
    const float* ta_w2   = (const float*)d_in[9];
    const float* ta_w3   = (const float*)d_in[10];
    const float* ta_bias = (const float*)d_in[11];
    const float* ta_proj = (const float*)d_in[12];
    const float* time_w  = (const float*)d_in[13];
    const float* time_b  = (const float*)d_in[14];
    const float* skip_w  = (const float*)d_in[15];
    const float* skip_b  = (const float*)d_in[16];
    const float* ln_g    = (const float*)d_in[17];
    const float* ln_b    = (const float*)d_in[18];
    float* out = (float*)d_out;

    // temporal attention
    rhs_t_kernel<<<B_ * N_, 128>>>(x, ta_w3);
    tmp_bt_part_kernel<<<dim3(8, B_), 768>>>(x, ta_w1);
    tmp_bt_reduce_kernel<<<(B_ * 768 + 255) / 256, 256>>>();
    lhs_t_kernel<<<(B_ * T_ * N_ + 255) / 256, 256>>>(ta_w2);
    temporal_attn_kernel<<<B_, 576>>>(ta_bias, ta_proj);
    xtemp_kernel<<<(B_ * N_ * F_ * T_ + 255) / 256, 256>>>(x);

    // operand conversions independent of the attention chain
    convX_kernel<<<dim3(16, 24, B_), dim3(32, 8)>>>(x);
    conv_proj_kernel<<<1024, 256>>>(sa_proj);

    // spatial attention (bf16-split mma S chain)
    spre_kernel<<<B_ * N_, 128>>>(sa_wa, sa_wb, sa_wc);
    spatial_scores_kernel<<<dim3(32, 32, B_), dim3(16, 16)>>>(sa_bias);
    S_mma_kernel<<<dim3(8, 8, B_), 128>>>();
    spat_softmax_kernel<<<(B_ * N_ + 255) / 256, 256>>>();

    // chebyshev graph conv via bf16-split mma.sync
    convA_kernel<<<dim3(16, 16, 96), dim3(32, 8)>>>(cheb);
    cheb_mma_kernel<<<dim3(12, 8, B_), 128>>>();

    // fused epilogue
    final_kernel<<<B_ * N_, 128>>>(x, w_cheb, time_w, time_b, skip_w, skip_b, ln_g, ln_b, out);
}